// round 3
// baseline (speedup 1.0000x reference)
#include <cuda_runtime.h>
#include <math.h>

#define FULLMASK 0xffffffffu
typedef unsigned long long ull;

// Coefficients of k_1..k_{s+1} used to build the input of the NEXT stage
// (rows 0..4 = A-rows 2..6, row 5 = B row for the final update).
__constant__ float CT[6][6] = {
    {0.161f, 0.f, 0.f, 0.f, 0.f, 0.f},
    {(float)(-0.008480655492356989), (float)(0.335480655492357), 0.f, 0.f, 0.f, 0.f},
    {(float)(2.8971530571054935), (float)(-6.359448489975075), (float)(4.3622954328695815), 0.f, 0.f, 0.f},
    {(float)(5.325864828439257), (float)(-11.748883564062828), (float)(7.4955393428898365), (float)(-0.09249506636175525), 0.f, 0.f},
    {(float)(5.86145544294642), (float)(-12.92096931784711), (float)(8.159367898576159), (float)(-0.071584973281401), (float)(-0.028269050394068383)},
    {(float)(0.09646076681806523), 0.01f, (float)(0.4798896504144996), (float)(1.379008574103742), (float)(-3.290069515436081), (float)(2.324710524099774)}
};

static __device__ __forceinline__ float softplus_f(float x) {
    // matches jax.nn.softplus = max(x,0) + log1p(exp(-|x|))
    return fmaxf(x, 0.0f) + log1pf(expf(-fabsf(x)));
}
static __device__ __forceinline__ float sigmoid_f(float x) {
    return 1.0f / (1.0f + expf(-x));
}

static __device__ __forceinline__ ull pack2(float lo, float hi) {
    ull r;
    asm("mov.b64 %0, {%1, %2};" : "=l"(r) : "f"(lo), "f"(hi));
    return r;
}
static __device__ __forceinline__ void unpack2(ull v, float& lo, float& hi) {
    asm("mov.b64 {%0, %1}, %2;" : "=f"(lo), "=f"(hi) : "l"(v));
}
#define FMA2(acc, a, b) asm("fma.rn.f32x2 %0, %1, %2, %0;" : "+l"(acc) : "l"(a), "l"(b))
#define ADD2(d, a, b)   asm("add.rn.f32x2 %0, %1, %2;"     : "=l"(d)  : "l"(a), "l"(b))

// State layout in all shared vectors: [0..63] = h (hidden), [64..68] = S,E,I,A,R
__global__ __launch_bounds__(512, 1)
void ode_persistent_kernel(
    const float* __restrict__ y0,   const float* __restrict__ ts,
    const float* __restrict__ gW0,  const float* __restrict__ gb0,
    const float* __restrict__ gW1,  const float* __restrict__ gb1,
    const float* __restrict__ gW2,  const float* __restrict__ gb2,
    const float* __restrict__ gW3,  const float* __restrict__ gb3,
    const float* __restrict__ gWhb, const float* __restrict__ gbhb,
    const float* __restrict__ ghv,  const float* __restrict__ gscale,
    float* __restrict__ out)
{
    const int t    = threadIdx.x;
    const int r01  = t >> 2;        // row for W0 / W1 / W2 (0..127)
    const int q    = t & 3;         // which quarter of the dot product
    const int r3   = t >> 3;        // row for W3 (0..63)
    const int e3   = t & 7;         // which eighth of the W3 dot
    const int warp = t >> 5;
    const int lane = t & 31;

    __shared__ __align__(16) float syin[72];   // current rhs input vector
    __shared__ __align__(16) float sy[72];     // base y of the current step
    __shared__ __align__(16) float sk[6][72];  // k_1..k_6
    __shared__ __align__(16) float sza[128];   // activation ping
    __shared__ __align__(16) float szb[128];   // activation pong
    __shared__ __align__(16) float swhb[64];
    __shared__ __align__(16) float sb0[128], sb1[128], sb2[128], sb3[64];
    __shared__ float sdt[200];

    float* out_state = out;          // (201, 5)
    float* out_h     = out + 201*5;  // (201, 64)

    // ---- load weights into registers as packed f32x2 (resident all run) ----
    ull w0p[8], w1p[16], w2p[16], w3p[8];
    {
        const float4* p0 = reinterpret_cast<const float4*>(gW0 + (r01 * 64 + q * 16));
        #pragma unroll
        for (int j = 0; j < 4; j++) {
            float4 v = p0[j];
            w0p[2*j]   = pack2(v.x, v.y);
            w0p[2*j+1] = pack2(v.z, v.w);
        }
        const float4* p1 = reinterpret_cast<const float4*>(gW1 + (r01 * 128 + q * 32));
        #pragma unroll
        for (int j = 0; j < 8; j++) {
            float4 v = p1[j];
            w1p[2*j]   = pack2(v.x, v.y);
            w1p[2*j+1] = pack2(v.z, v.w);
        }
        const float4* p2 = reinterpret_cast<const float4*>(gW2 + (r01 * 128 + q * 32));
        #pragma unroll
        for (int j = 0; j < 8; j++) {
            float4 v = p2[j];
            w2p[2*j]   = pack2(v.x, v.y);
            w2p[2*j+1] = pack2(v.z, v.w);
        }
        const float4* p3 = reinterpret_cast<const float4*>(gW3 + (r3 * 128 + e3 * 16));
        #pragma unroll
        for (int j = 0; j < 4; j++) {
            float4 v = p3[j];
            w3p[2*j]   = pack2(v.x, v.y);
            w3p[2*j+1] = pack2(v.z, v.w);
        }
    }
    const float scl = gscale[0];
    const float bhb = gbhb[0];

    // ---- biases to SMEM (saves registers), init state / dt / first save ----
    if (t < 128) { sb0[t] = gb0[t]; sb1[t] = gb1[t]; sb2[t] = gb2[t]; }
    if (t < 64) {
        sb3[t]  = gb3[t];
        swhb[t] = gWhb[t];
        float hv = ghv[t];
        sy[t] = hv; syin[t] = hv;
        out_h[t] = hv;              // save index 0, hidden part
    } else if (t >= 128 && t < 133) {
        float v = y0[t - 128];
        sy[t - 64] = v; syin[t - 64] = v;
        out_state[t - 128] = v;     // save index 0, state part
    }
    #pragma unroll 1
    for (int i = t; i < 200; i += 512) sdt[i] = (ts[i + 1] - ts[i]) * 0.02f;
    __syncthreads();

    // ---- main sequential integration ----
    #pragma unroll 1
    for (int iv = 0; iv < 200; iv++) {
        const float dt = sdt[iv];
        const int sidx = iv + 1;
        #pragma unroll 1
        for (int sub = 0; sub < 50; sub++) {
            const bool save = (sub == 49);
            #pragma unroll 1
            for (int s = 0; s < 6; s++) {
                // ===== Phase A: z0 = softplus(W0 @ h + b0); warp15: beta + dstate =====
                {
                    ull a0 = 0, a1 = 0, a2 = 0, a3 = 0;
                    const ulonglong2* hin = reinterpret_cast<const ulonglong2*>(syin + q * 16);
                    {
                        ulonglong2 z0v = hin[0], z1v = hin[1], z2v = hin[2], z3v = hin[3];
                        FMA2(a0, w0p[0], z0v.x); FMA2(a1, w0p[1], z0v.y);
                        FMA2(a2, w0p[2], z1v.x); FMA2(a3, w0p[3], z1v.y);
                        FMA2(a0, w0p[4], z2v.x); FMA2(a1, w0p[5], z2v.y);
                        FMA2(a2, w0p[6], z3v.x); FMA2(a3, w0p[7], z3v.y);
                    }
                    ull s01, s23, stot;
                    ADD2(s01, a0, a1); ADD2(s23, a2, a3); ADD2(stot, s01, s23);
                    float lo, hi; unpack2(stot, lo, hi);
                    float sacc = lo + hi;
                    sacc += __shfl_xor_sync(FULLMASK, sacc, 1);
                    sacc += __shfl_xor_sync(FULLMASK, sacc, 2);
                    if (q == 0) sza[r01] = softplus_f(sacc + sb0[r01]);

                    if (warp == 15) {
                        // beta = sigmoid(Whb @ h + bhb), computed redundantly per lane
                        ull c0 = 0, c1 = 0, c2 = 0, c3 = 0;
                        const ulonglong2* hh = reinterpret_cast<const ulonglong2*>(syin);
                        const ulonglong2* wv = reinterpret_cast<const ulonglong2*>(swhb);
                        #pragma unroll
                        for (int j = 0; j < 16; j += 2) {
                            ulonglong2 hv2 = hh[j],   wv2 = wv[j];
                            ulonglong2 hv3 = hh[j+1], wv3 = wv[j+1];
                            FMA2(c0, wv2.x, hv2.x); FMA2(c1, wv2.y, hv2.y);
                            FMA2(c2, wv3.x, hv3.x); FMA2(c3, wv3.y, hv3.y);
                        }
                        ull d01, d23, dtot;
                        ADD2(d01, c0, c1); ADD2(d23, c2, c3); ADD2(dtot, d01, d23);
                        float dlo, dhi; unpack2(dtot, dlo, dhi);
                        float beta = sigmoid_f(dlo + dhi + bhb);
                        if (lane == 0) {
                            float Sv = syin[64], Ev = syin[65], Iv = syin[66], Av = syin[67];
                            float LL  = 0.5f * Iv + Av;             // ee=0, (1-q)=0.5, dd=1
                            float bsl = (beta * Sv) * LL;
                            sk[s][64] = -bsl;                                        // dS
                            sk[s][65] = bsl - 0.526f * Ev;                           // dE
                            sk[s][66] = (float)(0.667 * 0.526) * Ev - 0.244f * Iv;   // dI
                            sk[s][67] = (float)((1.0 - 0.667) * 0.526) * Ev - 0.244f * Av; // dA
                            sk[s][68] = (float)(0.98 * 0.244) * Iv + 0.244f * Av;    // dR
                        }
                    }
                }
                __syncthreads();

                // ===== Phase B: z1 = softplus(W1 @ z0 + b1) =====
                {
                    ull a0 = 0, a1 = 0, a2 = 0, a3 = 0;
                    const ulonglong2* zin = reinterpret_cast<const ulonglong2*>(sza + q * 32);
                    #pragma unroll
                    for (int j = 0; j < 8; j += 2) {
                        ulonglong2 z0v = zin[j], z1v = zin[j+1];
                        FMA2(a0, w1p[2*j+0], z0v.x); FMA2(a1, w1p[2*j+1], z0v.y);
                        FMA2(a2, w1p[2*j+2], z1v.x); FMA2(a3, w1p[2*j+3], z1v.y);
                    }
                    ull s01, s23, stot;
                    ADD2(s01, a0, a1); ADD2(s23, a2, a3); ADD2(stot, s01, s23);
                    float lo, hi; unpack2(stot, lo, hi);
                    float sacc = lo + hi;
                    sacc += __shfl_xor_sync(FULLMASK, sacc, 1);
                    sacc += __shfl_xor_sync(FULLMASK, sacc, 2);
                    if (q == 0) szb[r01] = softplus_f(sacc + sb1[r01]);
                }
                __syncthreads();

                // ===== Phase C: z2 = softplus(W2 @ z1 + b2) =====
                {
                    ull a0 = 0, a1 = 0, a2 = 0, a3 = 0;
                    const ulonglong2* zin = reinterpret_cast<const ulonglong2*>(szb + q * 32);
                    #pragma unroll
                    for (int j = 0; j < 8; j += 2) {
                        ulonglong2 z0v = zin[j], z1v = zin[j+1];
                        FMA2(a0, w2p[2*j+0], z0v.x); FMA2(a1, w2p[2*j+1], z0v.y);
                        FMA2(a2, w2p[2*j+2], z1v.x); FMA2(a3, w2p[2*j+3], z1v.y);
                    }
                    ull s01, s23, stot;
                    ADD2(s01, a0, a1); ADD2(s23, a2, a3); ADD2(stot, s01, s23);
                    float lo, hi; unpack2(stot, lo, hi);
                    float sacc = lo + hi;
                    sacc += __shfl_xor_sync(FULLMASK, sacc, 1);
                    sacc += __shfl_xor_sync(FULLMASK, sacc, 2);
                    if (q == 0) sza[r01] = softplus_f(sacc + sb2[r01]);
                }
                __syncthreads();

                // ===== Phase D: o = W3 @ z2 + b3; dh; write k_s and next-stage input =====
                {
                    ull a0 = 0, a1 = 0, a2 = 0, a3 = 0;
                    const ulonglong2* zin = reinterpret_cast<const ulonglong2*>(sza + e3 * 16);
                    {
                        ulonglong2 z0v = zin[0], z1v = zin[1], z2v = zin[2], z3v = zin[3];
                        FMA2(a0, w3p[0], z0v.x); FMA2(a1, w3p[1], z0v.y);
                        FMA2(a2, w3p[2], z1v.x); FMA2(a3, w3p[3], z1v.y);
                        FMA2(a0, w3p[4], z2v.x); FMA2(a1, w3p[5], z2v.y);
                        FMA2(a2, w3p[6], z3v.x); FMA2(a3, w3p[7], z3v.y);
                    }
                    ull s01, s23, stot;
                    ADD2(s01, a0, a1); ADD2(s23, a2, a3); ADD2(stot, s01, s23);
                    float lo, hi; unpack2(stot, lo, hi);
                    float sacc = lo + hi;
                    sacc += __shfl_xor_sync(FULLMASK, sacc, 1);
                    sacc += __shfl_xor_sync(FULLMASK, sacc, 2);
                    sacc += __shfl_xor_sync(FULLMASK, sacc, 4);

                    if (e3 == 0) {
                        float o  = sacc + sb3[r3];
                        float kc = scl * tanhf(1e-4f * o);
                        sk[s][r3] = kc;
                        float comb = CT[s][s] * kc;
                        #pragma unroll 1
                        for (int i = 0; i < s; i++) comb = fmaf(CT[s][i], sk[i][r3], comb);
                        float yn = fmaf(dt, comb, sy[r3]);
                        syin[r3] = yn;
                        if (s == 5) {
                            sy[r3] = yn;
                            if (save) out_h[sidx * 64 + r3] = yn;
                        }
                    } else if (e3 == 1 && r3 < 5) {
                        int j = 64 + r3;
                        float kc = sk[s][j];   // written in phase A, visible after barriers
                        float comb = CT[s][s] * kc;
                        #pragma unroll 1
                        for (int i = 0; i < s; i++) comb = fmaf(CT[s][i], sk[i][j], comb);
                        float yn = fmaf(dt, comb, sy[j]);
                        syin[j] = yn;
                        if (s == 5) {
                            sy[j] = yn;
                            if (save) out_state[sidx * 5 + r3] = yn;
                        }
                    }
                }
                __syncthreads();
            } // stages
        } // substeps
    } // intervals
}

extern "C" void kernel_launch(void* const* d_in, const int* in_sizes, int n_in,
                              void* d_out, int out_size) {
    (void)in_sizes; (void)n_in; (void)out_size;
    const float* y0   = (const float*)d_in[0];
    const float* ts   = (const float*)d_in[1];
    const float* W0   = (const float*)d_in[2];
    const float* b0   = (const float*)d_in[3];
    const float* W1   = (const float*)d_in[4];
    const float* b1   = (const float*)d_in[5];
    const float* W2   = (const float*)d_in[6];
    const float* b2   = (const float*)d_in[7];
    const float* W3   = (const float*)d_in[8];
    const float* b3   = (const float*)d_in[9];
    const float* Whb  = (const float*)d_in[10];
    const float* bhb  = (const float*)d_in[11];
    const float* hv   = (const float*)d_in[12];
    const float* scal = (const float*)d_in[13];
    float* out = (float*)d_out;

    ode_persistent_kernel<<<1, 512>>>(y0, ts, W0, b0, W1, b1, W2, b2, W3, b3,
                                      Whb, bhb, hv, scal, out);
}

// round 4
// speedup vs baseline: 1.0295x; 1.0295x over previous
#include <cuda_runtime.h>
#include <math.h>

#define FULLMASK 0xffffffffu
typedef unsigned long long ull;

// Coefficients of k_1..k_{s+1} used to build the input of the NEXT stage
// (rows 0..4 = A-rows 2..6, row 5 = B row for the final update).
__constant__ float CT[6][6] = {
    {0.161f, 0.f, 0.f, 0.f, 0.f, 0.f},
    {(float)(-0.008480655492356989), (float)(0.335480655492357), 0.f, 0.f, 0.f, 0.f},
    {(float)(2.8971530571054935), (float)(-6.359448489975075), (float)(4.3622954328695815), 0.f, 0.f, 0.f},
    {(float)(5.325864828439257), (float)(-11.748883564062828), (float)(7.4955393428898365), (float)(-0.09249506636175525), 0.f, 0.f},
    {(float)(5.86145544294642), (float)(-12.92096931784711), (float)(8.159367898576159), (float)(-0.071584973281401), (float)(-0.028269050394068383), 0.f},
    {(float)(0.09646076681806523), 0.01f, (float)(0.4798896504144996), (float)(1.379008574103742), (float)(-3.290069515436081), (float)(2.324710524099774)}
};

static __device__ __forceinline__ float softplus_f(float x) {
    // softplus = max(x,0) + log1p(exp(-|x|)); arg of log is in (1,2] so __logf is accurate
    return fmaxf(x, 0.0f) + __logf(1.0f + __expf(-fabsf(x)));
}
static __device__ __forceinline__ float sigmoid_f(float x) {
    return 1.0f / (1.0f + __expf(-x));
}

static __device__ __forceinline__ ull pack2(float lo, float hi) {
    ull r;
    asm("mov.b64 %0, {%1, %2};" : "=l"(r) : "f"(lo), "f"(hi));
    return r;
}
static __device__ __forceinline__ void unpack2(ull v, float& lo, float& hi) {
    asm("mov.b64 {%0, %1}, %2;" : "=f"(lo), "=f"(hi) : "l"(v));
}
#define FMA2(acc, a, b) asm("fma.rn.f32x2 %0, %1, %2, %0;" : "+l"(acc) : "l"(a), "l"(b))
#define ADD2(d, a, b)   asm("add.rn.f32x2 %0, %1, %2;"     : "=l"(d)  : "l"(a), "l"(b))

// State layout in all shared state vectors: [0..63] = h, [64..68] = S,E,I,A,R
__global__ __launch_bounds__(512, 1)
void ode_persistent_kernel(
    const float* __restrict__ y0,   const float* __restrict__ ts,
    const float* __restrict__ gW0,  const float* __restrict__ gb0,
    const float* __restrict__ gW1,  const float* __restrict__ gb1,
    const float* __restrict__ gW2,  const float* __restrict__ gb2,
    const float* __restrict__ gW3,  const float* __restrict__ gb3,
    const float* __restrict__ gWhb, const float* __restrict__ gbhb,
    const float* __restrict__ ghv,  const float* __restrict__ gscale,
    float* __restrict__ out)
{
    const int t    = threadIdx.x;
    const int r01  = t >> 2;        // row for W0 / W1 / W2 (0..127)
    const int q    = t & 3;         // quarter of the dot product
    const int r3   = t >> 3;        // row for W3 (0..63)
    const int e3   = t & 7;         // eighth of the W3 dot
    const int warp = t >> 5;
    const int lane = t & 31;

    // Dynamic SMEM: W0 and W3 thread-interleaved (coalesced LDS.128), 64 KB
    extern __shared__ __align__(16) unsigned char dynsmem[];
    ulonglong2* sw0 = reinterpret_cast<ulonglong2*>(dynsmem);            // [4][512]
    ulonglong2* sw3 = reinterpret_cast<ulonglong2*>(dynsmem) + 4 * 512;  // [4][512]

    __shared__ __align__(16) float syin[72];   // current rhs input vector
    __shared__ __align__(16) float sy[72];     // base y of the current step
    __shared__ __align__(16) float sk[6][72];  // k_1..k_6 (state part; hidden uses it too)
    __shared__ __align__(16) float sza[128];   // activation ping
    __shared__ __align__(16) float szb[128];   // activation pong
    __shared__ __align__(16) float swhb[64];
    __shared__ __align__(16) float sb0[128], sb1[128], sb2[128], sb3[64];
    __shared__ float sdt[200];

    float* out_state = out;          // (201, 5)
    float* out_h     = out + 201*5;  // (201, 64)

    // ---- W1/W2 chunks into registers (64 regs/thread, resident all run) ----
    ull w1p[16], w2p[16];
    {
        const float4* p1 = reinterpret_cast<const float4*>(gW1 + (r01 * 128 + q * 32));
        #pragma unroll
        for (int j = 0; j < 8; j++) {
            float4 v = p1[j];
            w1p[2*j]   = pack2(v.x, v.y);
            w1p[2*j+1] = pack2(v.z, v.w);
        }
        const float4* p2 = reinterpret_cast<const float4*>(gW2 + (r01 * 128 + q * 32));
        #pragma unroll
        for (int j = 0; j < 8; j++) {
            float4 v = p2[j];
            w2p[2*j]   = pack2(v.x, v.y);
            w2p[2*j+1] = pack2(v.z, v.w);
        }
    }
    // ---- W0/W3 chunks into interleaved SMEM ----
    {
        const float4* p0 = reinterpret_cast<const float4*>(gW0 + (r01 * 64 + q * 16));
        #pragma unroll
        for (int j = 0; j < 4; j++) {
            float4 v = p0[j];
            ulonglong2 u;
            u.x = pack2(v.x, v.y);
            u.y = pack2(v.z, v.w);
            sw0[j * 512 + t] = u;
        }
        const float4* p3 = reinterpret_cast<const float4*>(gW3 + (r3 * 128 + e3 * 16));
        #pragma unroll
        for (int j = 0; j < 4; j++) {
            float4 v = p3[j];
            ulonglong2 u;
            u.x = pack2(v.x, v.y);
            u.y = pack2(v.z, v.w);
            sw3[j * 512 + t] = u;
        }
    }
    const float scl = gscale[0];
    const float bhb = gbhb[0];

    // ---- biases, Whb, init state / dt / first save ----
    if (t < 128) { sb0[t] = gb0[t]; sb1[t] = gb1[t]; sb2[t] = gb2[t]; }
    if (t < 64) {
        sb3[t]  = gb3[t];
        swhb[t] = gWhb[t];
        float hv = ghv[t];
        sy[t] = hv; syin[t] = hv;
        out_h[t] = hv;              // save index 0, hidden part
    } else if (t >= 128 && t < 133) {
        float v = y0[t - 128];
        sy[t - 64] = v; syin[t - 64] = v;
        out_state[t - 128] = v;     // save index 0, state part
    }
    #pragma unroll 1
    for (int i = t; i < 200; i += 512) sdt[i] = (ts[i + 1] - ts[i]) * 0.02f;
    __syncthreads();

    // ---- main sequential integration ----
    #pragma unroll 1
    for (int iv = 0; iv < 200; iv++) {
        const float dt = sdt[iv];
        const int sidx = iv + 1;
        #pragma unroll 1
        for (int sub = 0; sub < 50; sub++) {
            const bool save = (sub == 49);
            #pragma unroll 1
            for (int s = 0; s < 6; s++) {
                // ===== Phase A: z0 = softplus(W0 @ h + b0); warp15: beta + dstate =====
                {
                    ulonglong2 wa0 = sw0[t], wa1 = sw0[512 + t];
                    ulonglong2 wa2 = sw0[1024 + t], wa3 = sw0[1536 + t];
                    const ulonglong2* hin = reinterpret_cast<const ulonglong2*>(syin + (q << 4));
                    ulonglong2 h0 = hin[0], h1 = hin[1], h2 = hin[2], h3 = hin[3];
                    ull a0 = 0, a1 = 0, a2 = 0, a3 = 0;
                    FMA2(a0, wa0.x, h0.x); FMA2(a1, wa0.y, h0.y);
                    FMA2(a2, wa1.x, h1.x); FMA2(a3, wa1.y, h1.y);
                    FMA2(a0, wa2.x, h2.x); FMA2(a1, wa2.y, h2.y);
                    FMA2(a2, wa3.x, h3.x); FMA2(a3, wa3.y, h3.y);
                    ull s01, s23, stot;
                    ADD2(s01, a0, a1); ADD2(s23, a2, a3); ADD2(stot, s01, s23);
                    float lo, hi; unpack2(stot, lo, hi);
                    float sacc = lo + hi;
                    sacc += __shfl_xor_sync(FULLMASK, sacc, 1);
                    sacc += __shfl_xor_sync(FULLMASK, sacc, 2);
                    if (q == 0) sza[r01] = softplus_f(sacc + sb0[r01]);

                    if (warp == 15) {
                        // beta dot split across lanes: 2 elements per lane + butterfly
                        ull hv2 = *reinterpret_cast<const ull*>(syin + 2 * lane);
                        ull wv2 = *reinterpret_cast<const ull*>(swhb + 2 * lane);
                        ull c = 0; FMA2(c, wv2, hv2);
                        float clo, chi; unpack2(c, clo, chi);
                        float bs = clo + chi;
                        bs += __shfl_xor_sync(FULLMASK, bs, 1);
                        bs += __shfl_xor_sync(FULLMASK, bs, 2);
                        bs += __shfl_xor_sync(FULLMASK, bs, 4);
                        bs += __shfl_xor_sync(FULLMASK, bs, 8);
                        bs += __shfl_xor_sync(FULLMASK, bs, 16);
                        if (lane == 0) {
                            float beta = sigmoid_f(bs + bhb);
                            float Sv = syin[64], Ev = syin[65], Iv = syin[66], Av = syin[67];
                            float LL  = 0.5f * Iv + Av;             // ee=0, (1-q)=0.5, dd=1
                            float bsl = (beta * Sv) * LL;
                            sk[s][64] = -bsl;                                        // dS
                            sk[s][65] = bsl - 0.526f * Ev;                           // dE
                            sk[s][66] = (float)(0.667 * 0.526) * Ev - 0.244f * Iv;   // dI
                            sk[s][67] = (float)((1.0 - 0.667) * 0.526) * Ev - 0.244f * Av; // dA
                            sk[s][68] = (float)(0.98 * 0.244) * Iv + 0.244f * Av;    // dR
                        }
                    }
                }
                __syncthreads();

                // ===== Phase B: z1 = softplus(W1 @ z0 + b1)  (weights in regs) =====
                {
                    ull a0 = 0, a1 = 0, a2 = 0, a3 = 0;
                    const ulonglong2* zin = reinterpret_cast<const ulonglong2*>(sza + (q << 5));
                    #pragma unroll
                    for (int j = 0; j < 8; j += 2) {
                        ulonglong2 z0v = zin[j], z1v = zin[j+1];
                        FMA2(a0, w1p[2*j+0], z0v.x); FMA2(a1, w1p[2*j+1], z0v.y);
                        FMA2(a2, w1p[2*j+2], z1v.x); FMA2(a3, w1p[2*j+3], z1v.y);
                    }
                    ull s01, s23, stot;
                    ADD2(s01, a0, a1); ADD2(s23, a2, a3); ADD2(stot, s01, s23);
                    float lo, hi; unpack2(stot, lo, hi);
                    float sacc = lo + hi;
                    sacc += __shfl_xor_sync(FULLMASK, sacc, 1);
                    sacc += __shfl_xor_sync(FULLMASK, sacc, 2);
                    if (q == 0) szb[r01] = softplus_f(sacc + sb1[r01]);
                }
                __syncthreads();

                // ===== Phase C: z2 = softplus(W2 @ z1 + b2)  (weights in regs) =====
                {
                    ull a0 = 0, a1 = 0, a2 = 0, a3 = 0;
                    const ulonglong2* zin = reinterpret_cast<const ulonglong2*>(szb + (q << 5));
                    #pragma unroll
                    for (int j = 0; j < 8; j += 2) {
                        ulonglong2 z0v = zin[j], z1v = zin[j+1];
                        FMA2(a0, w2p[2*j+0], z0v.x); FMA2(a1, w2p[2*j+1], z0v.y);
                        FMA2(a2, w2p[2*j+2], z1v.x); FMA2(a3, w2p[2*j+3], z1v.y);
                    }
                    ull s01, s23, stot;
                    ADD2(s01, a0, a1); ADD2(s23, a2, a3); ADD2(stot, s01, s23);
                    float lo, hi; unpack2(stot, lo, hi);
                    float sacc = lo + hi;
                    sacc += __shfl_xor_sync(FULLMASK, sacc, 1);
                    sacc += __shfl_xor_sync(FULLMASK, sacc, 2);
                    if (q == 0) sza[r01] = softplus_f(sacc + sb2[r01]);
                }
                __syncthreads();

                // ===== Phase D: o = W3 @ z2 + b3; dh; write k_s and next-stage input =====
                {
                    ulonglong2 wd0 = sw3[t], wd1 = sw3[512 + t];
                    ulonglong2 wd2 = sw3[1024 + t], wd3 = sw3[1536 + t];
                    const ulonglong2* zin = reinterpret_cast<const ulonglong2*>(sza + (e3 << 4));
                    ulonglong2 z0v = zin[0], z1v = zin[1], z2v = zin[2], z3v = zin[3];
                    ull a0 = 0, a1 = 0, a2 = 0, a3 = 0;
                    FMA2(a0, wd0.x, z0v.x); FMA2(a1, wd0.y, z0v.y);
                    FMA2(a2, wd1.x, z1v.x); FMA2(a3, wd1.y, z1v.y);
                    FMA2(a0, wd2.x, z2v.x); FMA2(a1, wd2.y, z2v.y);
                    FMA2(a2, wd3.x, z3v.x); FMA2(a3, wd3.y, z3v.y);
                    ull s01, s23, stot;
                    ADD2(s01, a0, a1); ADD2(s23, a2, a3); ADD2(stot, s01, s23);
                    float lo, hi; unpack2(stot, lo, hi);
                    float sacc = lo + hi;
                    sacc += __shfl_xor_sync(FULLMASK, sacc, 1);
                    sacc += __shfl_xor_sync(FULLMASK, sacc, 2);
                    sacc += __shfl_xor_sync(FULLMASK, sacc, 4);

                    if (e3 == 0) {
                        float o  = sacc + sb3[r3];
                        float kc = scl * tanhf(1e-4f * o);
                        sk[s][r3] = kc;
                        float comb = CT[s][s] * kc;
                        #pragma unroll 1
                        for (int i = 0; i < s; i++) comb = fmaf(CT[s][i], sk[i][r3], comb);
                        float yn = fmaf(dt, comb, sy[r3]);
                        syin[r3] = yn;
                        if (s == 5) {
                            sy[r3] = yn;
                            if (save) out_h[sidx * 64 + r3] = yn;
                        }
                    } else if (e3 == 1 && r3 < 5) {
                        int j = 64 + r3;
                        float kc = sk[s][j];   // written in phase A, visible after barriers
                        float comb = CT[s][s] * kc;
                        #pragma unroll 1
                        for (int i = 0; i < s; i++) comb = fmaf(CT[s][i], sk[i][j], comb);
                        float yn = fmaf(dt, comb, sy[j]);
                        syin[j] = yn;
                        if (s == 5) {
                            sy[j] = yn;
                            if (save) out_state[sidx * 5 + r3] = yn;
                        }
                    }
                }
                __syncthreads();
            } // stages
        } // substeps
    } // intervals
}

extern "C" void kernel_launch(void* const* d_in, const int* in_sizes, int n_in,
                              void* d_out, int out_size) {
    (void)in_sizes; (void)n_in; (void)out_size;
    const float* y0   = (const float*)d_in[0];
    const float* ts   = (const float*)d_in[1];
    const float* W0   = (const float*)d_in[2];
    const float* b0   = (const float*)d_in[3];
    const float* W1   = (const float*)d_in[4];
    const float* b1   = (const float*)d_in[5];
    const float* W2   = (const float*)d_in[6];
    const float* b2   = (const float*)d_in[7];
    const float* W3   = (const float*)d_in[8];
    const float* b3   = (const float*)d_in[9];
    const float* Whb  = (const float*)d_in[10];
    const float* bhb  = (const float*)d_in[11];
    const float* hv   = (const float*)d_in[12];
    const float* scal = (const float*)d_in[13];
    float* out = (float*)d_out;

    const int dyn_smem = 2 * 4 * 512 * 16;  // sw0 + sw3 = 64 KB
    cudaFuncSetAttribute(ode_persistent_kernel,
                         cudaFuncAttributeMaxDynamicSharedMemorySize, dyn_smem);
    ode_persistent_kernel<<<1, 512, dyn_smem>>>(y0, ts, W0, b0, W1, b1, W2, b2, W3, b3,
                                                Whb, bhb, hv, scal, out);
}

// round 5
// speedup vs baseline: 2.0047x; 1.9472x over previous
#include <cuda_runtime.h>
#include <math.h>

#define FULLMASK 0xffffffffu
typedef unsigned long long ull;

// Coefficients of k_1..k_{s+1} used to build the input of the NEXT stage
// (rows 0..4 = A-rows 2..6, row 5 = B row for the final update).
__constant__ float CT[6][6] = {
    {0.161f, 0.f, 0.f, 0.f, 0.f, 0.f},
    {(float)(-0.008480655492356989), (float)(0.335480655492357), 0.f, 0.f, 0.f, 0.f},
    {(float)(2.8971530571054935), (float)(-6.359448489975075), (float)(4.3622954328695815), 0.f, 0.f, 0.f},
    {(float)(5.325864828439257), (float)(-11.748883564062828), (float)(7.4955393428898365), (float)(-0.09249506636175525), 0.f, 0.f},
    {(float)(5.86145544294642), (float)(-12.92096931784711), (float)(8.159367898576159), (float)(-0.071584973281401), (float)(-0.028269050394068383), 0.f},
    {(float)(0.09646076681806523), 0.01f, (float)(0.4798896504144996), (float)(1.379008574103742), (float)(-3.290069515436081), (float)(2.324710524099774)}
};

static __device__ __forceinline__ float softplus_f(float x) {
    // softplus = max(x,0) + log1p(exp(-|x|)); log arg in (1,2] so __logf stays accurate
    return fmaxf(x, 0.0f) + __logf(1.0f + __expf(-fabsf(x)));
}
static __device__ __forceinline__ float sigmoid_f(float x) {
    return 1.0f / (1.0f + __expf(-x));
}

static __device__ __forceinline__ ull pack2(float lo, float hi) {
    ull r;
    asm("mov.b64 %0, {%1, %2};" : "=l"(r) : "f"(lo), "f"(hi));
    return r;
}
static __device__ __forceinline__ void unpack2(ull v, float& lo, float& hi) {
    asm("mov.b64 {%0, %1}, %2;" : "=f"(lo), "=f"(hi) : "l"(v));
}
#define FMA2(acc, a, b) asm("fma.rn.f32x2 %0, %1, %2, %0;" : "+l"(acc) : "l"(a), "l"(b))
#define ADD2(d, a, b)   asm("add.rn.f32x2 %0, %1, %2;"     : "=l"(d)  : "l"(a), "l"(b))

// State layout in shared state vectors: [0..63] = h, [64..68] = S,E,I,A,R
__global__ __launch_bounds__(256, 1)
void ode_persistent_kernel(
    const float* __restrict__ y0,   const float* __restrict__ ts,
    const float* __restrict__ gW0,  const float* __restrict__ gb0,
    const float* __restrict__ gW1,  const float* __restrict__ gb1,
    const float* __restrict__ gW2,  const float* __restrict__ gb2,
    const float* __restrict__ gW3,  const float* __restrict__ gb3,
    const float* __restrict__ gWhb, const float* __restrict__ gbhb,
    const float* __restrict__ ghv,  const float* __restrict__ gscale,
    float* __restrict__ out)
{
    const int t    = threadIdx.x;
    const int r01  = t >> 1;        // row for W0 / W1 / W2 (0..127)
    const int hf   = t & 1;         // half of the dot product
    const int r3   = t >> 2;        // row for W3 (0..63)
    const int q3   = t & 3;         // quarter of the W3 dot
    const int warp = t >> 5;
    const int lane = t & 31;

    __shared__ __align__(16) float syin[72];   // current rhs input vector
    __shared__ __align__(16) float sy[72];     // base y of the current step
    __shared__ __align__(16) float sk[6][72];  // k_1..k_6
    __shared__ __align__(16) float sza[128];   // activation ping
    __shared__ __align__(16) float szb[128];   // activation pong
    __shared__ __align__(16) float swhb[64];
    __shared__ __align__(16) float sb0[128], sb1[128], sb2[128], sb3[64];
    __shared__ float sdt[200];

    float* out_state = out;          // (201, 5)
    float* out_h     = out + 201*5;  // (201, 64)

    // ---- ALL weights into registers as packed f32x2: 96 regs/thread ----
    ull w0p[16], w1p[32], w2p[32], w3p[16];
    {
        const float4* p0 = reinterpret_cast<const float4*>(gW0 + (r01 * 64 + hf * 32));
        #pragma unroll
        for (int j = 0; j < 8; j++) {
            float4 v = p0[j];
            w0p[2*j]   = pack2(v.x, v.y);
            w0p[2*j+1] = pack2(v.z, v.w);
        }
        const float4* p1 = reinterpret_cast<const float4*>(gW1 + (r01 * 128 + hf * 64));
        #pragma unroll
        for (int j = 0; j < 16; j++) {
            float4 v = p1[j];
            w1p[2*j]   = pack2(v.x, v.y);
            w1p[2*j+1] = pack2(v.z, v.w);
        }
        const float4* p2 = reinterpret_cast<const float4*>(gW2 + (r01 * 128 + hf * 64));
        #pragma unroll
        for (int j = 0; j < 16; j++) {
            float4 v = p2[j];
            w2p[2*j]   = pack2(v.x, v.y);
            w2p[2*j+1] = pack2(v.z, v.w);
        }
        const float4* p3 = reinterpret_cast<const float4*>(gW3 + (r3 * 128 + q3 * 32));
        #pragma unroll
        for (int j = 0; j < 8; j++) {
            float4 v = p3[j];
            w3p[2*j]   = pack2(v.x, v.y);
            w3p[2*j+1] = pack2(v.z, v.w);
        }
    }
    const float scl = gscale[0];
    const float bhb = gbhb[0];

    // ---- biases to SMEM, init state / dt / first save ----
    if (t < 128) { sb0[t] = gb0[t]; sb1[t] = gb1[t]; sb2[t] = gb2[t]; }
    if (t < 64) {
        sb3[t]  = gb3[t];
        swhb[t] = gWhb[t];
        float hv = ghv[t];
        sy[t] = hv; syin[t] = hv;
        out_h[t] = hv;              // save index 0, hidden part
    } else if (t >= 128 && t < 133) {
        float v = y0[t - 128];
        sy[t - 64] = v; syin[t - 64] = v;
        out_state[t - 128] = v;     // save index 0, state part
    }
    #pragma unroll 1
    for (int i = t; i < 200; i += 256) sdt[i] = (ts[i + 1] - ts[i]) * 0.02f;
    __syncthreads();

    // ---- main sequential integration ----
    #pragma unroll 1
    for (int iv = 0; iv < 200; iv++) {
        const float dt = sdt[iv];
        const int sidx = iv + 1;
        #pragma unroll 1
        for (int sub = 0; sub < 50; sub++) {
            const bool save = (sub == 49);
            #pragma unroll 1
            for (int s = 0; s < 6; s++) {
                // ===== Phase A: z0 = softplus(W0 @ h + b0); warp7: beta + dstate =====
                {
                    ull a0 = 0, a1 = 0, a2 = 0, a3 = 0;
                    const ulonglong2* hin = reinterpret_cast<const ulonglong2*>(syin + (hf << 5));
                    #pragma unroll
                    for (int j = 0; j < 8; j += 2) {
                        ulonglong2 z0v = hin[j], z1v = hin[j+1];
                        FMA2(a0, w0p[2*j+0], z0v.x); FMA2(a1, w0p[2*j+1], z0v.y);
                        FMA2(a2, w0p[2*j+2], z1v.x); FMA2(a3, w0p[2*j+3], z1v.y);
                    }
                    ull s01, s23, stot;
                    ADD2(s01, a0, a1); ADD2(s23, a2, a3); ADD2(stot, s01, s23);
                    float lo, hi; unpack2(stot, lo, hi);
                    float sacc = lo + hi;
                    sacc += __shfl_xor_sync(FULLMASK, sacc, 1);
                    if (hf == 0) sza[r01] = softplus_f(sacc + sb0[r01]);

                    if (warp == 7) {
                        // beta dot split across lanes: 2 elements/lane + butterfly
                        ull hv2 = *reinterpret_cast<const ull*>(syin + 2 * lane);
                        ull wv2 = *reinterpret_cast<const ull*>(swhb + 2 * lane);
                        ull c = 0; FMA2(c, wv2, hv2);
                        float clo, chi; unpack2(c, clo, chi);
                        float bs = clo + chi;
                        bs += __shfl_xor_sync(FULLMASK, bs, 1);
                        bs += __shfl_xor_sync(FULLMASK, bs, 2);
                        bs += __shfl_xor_sync(FULLMASK, bs, 4);
                        bs += __shfl_xor_sync(FULLMASK, bs, 8);
                        bs += __shfl_xor_sync(FULLMASK, bs, 16);
                        if (lane == 0) {
                            float beta = sigmoid_f(bs + bhb);
                            float Sv = syin[64], Ev = syin[65], Iv = syin[66], Av = syin[67];
                            float LL  = 0.5f * Iv + Av;             // ee=0, (1-q)=0.5, dd=1
                            float bsl = (beta * Sv) * LL;
                            sk[s][64] = -bsl;                                        // dS
                            sk[s][65] = bsl - 0.526f * Ev;                           // dE
                            sk[s][66] = (float)(0.667 * 0.526) * Ev - 0.244f * Iv;   // dI
                            sk[s][67] = (float)((1.0 - 0.667) * 0.526) * Ev - 0.244f * Av; // dA
                            sk[s][68] = (float)(0.98 * 0.244) * Iv + 0.244f * Av;    // dR
                        }
                    }
                }
                __syncthreads();

                // ===== Phase B: z1 = softplus(W1 @ z0 + b1) =====
                {
                    ull a0 = 0, a1 = 0, a2 = 0, a3 = 0;
                    const ulonglong2* zin = reinterpret_cast<const ulonglong2*>(sza + (hf << 6));
                    #pragma unroll
                    for (int j = 0; j < 16; j += 2) {
                        ulonglong2 z0v = zin[j], z1v = zin[j+1];
                        FMA2(a0, w1p[2*j+0], z0v.x); FMA2(a1, w1p[2*j+1], z0v.y);
                        FMA2(a2, w1p[2*j+2], z1v.x); FMA2(a3, w1p[2*j+3], z1v.y);
                    }
                    ull s01, s23, stot;
                    ADD2(s01, a0, a1); ADD2(s23, a2, a3); ADD2(stot, s01, s23);
                    float lo, hi; unpack2(stot, lo, hi);
                    float sacc = lo + hi;
                    sacc += __shfl_xor_sync(FULLMASK, sacc, 1);
                    if (hf == 0) szb[r01] = softplus_f(sacc + sb1[r01]);
                }
                __syncthreads();

                // ===== Phase C: z2 = softplus(W2 @ z1 + b2) =====
                {
                    ull a0 = 0, a1 = 0, a2 = 0, a3 = 0;
                    const ulonglong2* zin = reinterpret_cast<const ulonglong2*>(szb + (hf << 6));
                    #pragma unroll
                    for (int j = 0; j < 16; j += 2) {
                        ulonglong2 z0v = zin[j], z1v = zin[j+1];
                        FMA2(a0, w2p[2*j+0], z0v.x); FMA2(a1, w2p[2*j+1], z0v.y);
                        FMA2(a2, w2p[2*j+2], z1v.x); FMA2(a3, w2p[2*j+3], z1v.y);
                    }
                    ull s01, s23, stot;
                    ADD2(s01, a0, a1); ADD2(s23, a2, a3); ADD2(stot, s01, s23);
                    float lo, hi; unpack2(stot, lo, hi);
                    float sacc = lo + hi;
                    sacc += __shfl_xor_sync(FULLMASK, sacc, 1);
                    if (hf == 0) sza[r01] = softplus_f(sacc + sb2[r01]);
                }
                __syncthreads();

                // ===== Phase D: o = W3 @ z2 + b3; dh; write k_s and next-stage input =====
                {
                    ull a0 = 0, a1 = 0, a2 = 0, a3 = 0;
                    const ulonglong2* zin = reinterpret_cast<const ulonglong2*>(sza + (q3 << 5));
                    #pragma unroll
                    for (int j = 0; j < 8; j += 2) {
                        ulonglong2 z0v = zin[j], z1v = zin[j+1];
                        FMA2(a0, w3p[2*j+0], z0v.x); FMA2(a1, w3p[2*j+1], z0v.y);
                        FMA2(a2, w3p[2*j+2], z1v.x); FMA2(a3, w3p[2*j+3], z1v.y);
                    }
                    ull s01, s23, stot;
                    ADD2(s01, a0, a1); ADD2(s23, a2, a3); ADD2(stot, s01, s23);
                    float lo, hi; unpack2(stot, lo, hi);
                    float sacc = lo + hi;
                    sacc += __shfl_xor_sync(FULLMASK, sacc, 1);
                    sacc += __shfl_xor_sync(FULLMASK, sacc, 2);

                    if (q3 == 0) {
                        float o  = sacc + sb3[r3];
                        float kc = scl * tanhf(1e-4f * o);
                        sk[s][r3] = kc;
                        float comb = CT[s][s] * kc;
                        #pragma unroll 1
                        for (int i = 0; i < s; i++) comb = fmaf(CT[s][i], sk[i][r3], comb);
                        float yn = fmaf(dt, comb, sy[r3]);
                        syin[r3] = yn;
                        if (s == 5) {
                            sy[r3] = yn;
                            if (save) out_h[sidx * 64 + r3] = yn;
                        }
                    } else if (q3 == 1 && r3 < 5) {
                        int j = 64 + r3;
                        float kc = sk[s][j];   // written in phase A, visible after barriers
                        float comb = CT[s][s] * kc;
                        #pragma unroll 1
                        for (int i = 0; i < s; i++) comb = fmaf(CT[s][i], sk[i][j], comb);
                        float yn = fmaf(dt, comb, sy[j]);
                        syin[j] = yn;
                        if (s == 5) {
                            sy[j] = yn;
                            if (save) out_state[sidx * 5 + r3] = yn;
                        }
                    }
                }
                __syncthreads();
            } // stages
        } // substeps
    } // intervals
}

extern "C" void kernel_launch(void* const* d_in, const int* in_sizes, int n_in,
                              void* d_out, int out_size) {
    (void)in_sizes; (void)n_in; (void)out_size;
    const float* y0   = (const float*)d_in[0];
    const float* ts   = (const float*)d_in[1];
    const float* W0   = (const float*)d_in[2];
    const float* b0   = (const float*)d_in[3];
    const float* W1   = (const float*)d_in[4];
    const float* b1   = (const float*)d_in[5];
    const float* W2   = (const float*)d_in[6];
    const float* b2   = (const float*)d_in[7];
    const float* W3   = (const float*)d_in[8];
    const float* b3   = (const float*)d_in[9];
    const float* Whb  = (const float*)d_in[10];
    const float* bhb  = (const float*)d_in[11];
    const float* hv   = (const float*)d_in[12];
    const float* scal = (const float*)d_in[13];
    float* out = (float*)d_out;

    ode_persistent_kernel<<<1, 256>>>(y0, ts, W0, b0, W1, b1, W2, b2, W3, b3,
                                      Whb, bhb, hv, scal, out);
}